// round 6
// baseline (speedup 1.0000x reference)
#include <cuda_runtime.h>
#include <cuda_bf16.h>
#include <cuda_fp16.h>
#include <cuda_fp8.h>
#include <cstdint>

// Problem constants
#define NH    96          // heads total
#define NEDGE 1537        // edge table rows (incl. padding row 0)
#define NDIST 5           // MULTI_HOP
#define NP1   129         // N+1
#define NSQ   (129*129)
#define PROW  128         // padded fp8 row stride (bytes)
#define DSTRIDE (NEDGE * PROW)   // bytes per distance table (fits int32)

#define P_SCALE 64.0f     // fp8 table pre-scale

// Projected edge table, fp8 e4m3, scaled by P_SCALE, row-padded to 128B.
__device__ __align__(128) unsigned char g_P8[(size_t)NDIST * DSTRIDE];
// Spatial bias table in fp16: 512*96 entries.
__device__ __align__(16) __half g_SPh[512 * NH];

// hop normalizer with the fp8 scale folded in: 1/(3*sp*P_SCALE)
__constant__ float c_scale[6] = {0.f,
    1.f/(3.f*P_SCALE), 1.f/(6.f*P_SCALE), 1.f/(9.f*P_SCALE),
    1.f/(12.f*P_SCALE), 1.f/(15.f*P_SCALE)};

// per-r table base offsets (d = r/3)
__constant__ unsigned c_doff[15] = {
    0, 0, 0,
    1u*DSTRIDE, 1u*DSTRIDE, 1u*DSTRIDE,
    2u*DSTRIDE, 2u*DSTRIDE, 2u*DSTRIDE,
    3u*DSTRIDE, 3u*DSTRIDE, 3u*DSTRIDE,
    4u*DSTRIDE, 4u*DSTRIDE, 4u*DSTRIDE};

// ---------------------------------------------------------------------------
// Kernel 1 (merged prep): blocks 0..244 -> projected-table GEMM (32 edges per
// block: d = bx/49, e0 = (bx%49)*32); blocks 245..260 -> spatial f32->f16.
// ---------------------------------------------------------------------------
__global__ void prep_kernel(const float* __restrict__ enc,
                            const float* __restrict__ dis,
                            const float* __restrict__ sp) {
    const int bx = blockIdx.x;
    const int h  = threadIdx.x;          // 0..95

    if (bx < 245) {
        __shared__ float s_enc[32 * 32];
        const int d  = bx / 49;
        const int e0 = (bx - d * 49) * 32;

        float w[32];
#pragma unroll
        for (int k = 0; k < 32; ++k)
            w[k] = dis[(d * 32 + k) * NH + h];   // coalesced over h

        for (int i = h; i < 32 * 32; i += 96) {
            const int e = e0 + (i >> 5);
            s_enc[i] = (e < NEDGE) ? enc[e * 32 + (i & 31)] : 0.f;
        }
        __syncthreads();

#pragma unroll 4
        for (int ei = 0; ei < 32; ++ei) {
            const int e = e0 + ei;
            if (e >= NEDGE) break;
            float acc = 0.f;
#pragma unroll
            for (int k = 0; k < 32; ++k)
                acc += s_enc[ei * 32 + k] * w[k];
            g_P8[(size_t)d * DSTRIDE + e * PROW + h] =
                __nv_cvt_float_to_fp8(acc * P_SCALE, __NV_SATFINITE, __NV_E4M3);
        }
    } else {
        const int t0 = ((bx - 245) * 96 + h) * 32;
#pragma unroll 8
        for (int k = 0; k < 32; ++k)
            g_SPh[t0 + k] = __float2half(sp[t0 + k]);
    }
}

// fp8x2 pair -> half2 accumulate (low / high 16 bits of a word)
__device__ __forceinline__ void acc_word(__half2& lo, __half2& hi, uint32_t w) {
    lo = __hadd2(lo, __half2(__nv_cvt_fp8x2_to_halfraw2(
             (__nv_fp8x2_storage_t)(unsigned short)w, __NV_E4M3)));
    hi = __hadd2(hi, __half2(__nv_cvt_fp8x2_to_halfraw2(
             (__nv_fp8x2_storage_t)(w >> 16), __NV_E4M3)));
}

// ---------------------------------------------------------------------------
// Kernel 2: main. grid (129, 16); n==128 is the virtual-token row.
// Gather: (m, head-chunk) flattened to 96 slots = 3 full-warp iterations;
//   each slot = 16 heads; the 15 row-gathers issue as two hoisted batches
//   (8 + 7 LDG.128 in flight).
// Write: warp w owns head-PAIR hp = w+8k (h = 2hp, 2hp+1), half2 smem reads,
//   two contiguous 129-wide output rows (ob, ob+NSQ) per step.
// ---------------------------------------------------------------------------
__global__ __launch_bounds__(256, 4) void main_kernel(
    const float* __restrict__ attn_bias,
    const int*   __restrict__ spatial_pos,
    const int*   __restrict__ edge_input,
    const float* __restrict__ virt_w,
    float* __restrict__ out)
{
    const int n    = blockIdx.x;
    const int b    = blockIdx.y;
    const int tid  = threadIdx.x;

    if (n == 128) {
        for (int idx = tid; idx < NH * NP1; idx += 256) {
            const int h = idx / NP1;
            const int j = idx - h * NP1;
            const size_t o = ((((size_t)(h >> 3) * 16 + b) * 8) + (h & 7)) * NSQ + j;
            out[o] = 2.f * attn_bias[(size_t)b * NSQ + j] + virt_w[h];
        }
        return;
    }

    __shared__ __half sval[128 * 98];   // 196B row stride, conflict-free cols
    __shared__ int    s_idx[128 * 15];
    __shared__ int    s_sp[128];
    __shared__ float  s_ab[NP1];        // holds 2*attn_bias row
    __shared__ float  s_virt[NH];

    const int warp = tid >> 5;
    const int lane = tid & 31;
    const size_t bn = (size_t)(b * 128 + n) * 128;

    // stage indices: 1920 ints = 480 int4
    {
        const int4* gs = reinterpret_cast<const int4*>(edge_input + bn * 15);
        int4* ds = reinterpret_cast<int4*>(s_idx);
        ds[tid] = gs[tid];
        if (tid < 224) ds[256 + tid] = gs[256 + tid];
    }
    if (tid < 128) s_sp[tid] = spatial_pos[bn + tid];
    if (tid < NH)  s_virt[tid] = virt_w[tid];
    if (tid < NP1) s_ab[tid] = 2.f * attn_bias[(size_t)b * NSQ + (size_t)(n + 1) * NP1 + tid];
    __syncthreads();

    // ---- gather phase: 3 iterations x 32 lanes = 96 slots = 16 m x 6 chunks
    const __half2 hz = __float2half2_rn(0.f);
#pragma unroll
    for (int it = 0; it < 3; ++it) {
        const int slot  = it * 32 + lane;      // 0..95
        const int ml    = slot / 6;            // 0..15
        const int chunk = slot - ml * 6;       // 0..5
        const int m     = warp * 16 + ml;
        const unsigned char* pb = g_P8 + chunk * 16;
        const int* ip = s_idx + m * 15;

        __half2 a0 = hz, a1 = hz, a2 = hz, a3 = hz;
        __half2 a4 = hz, a5 = hz, a6 = hz, a7 = hz;

        // batch 1: 8 loads in flight
        uint4 v[8];
#pragma unroll
        for (int r = 0; r < 8; ++r)
            v[r] = *reinterpret_cast<const uint4*>(
                pb + ((unsigned)ip[r] * PROW + c_doff[r]));
#pragma unroll
        for (int r = 0; r < 8; ++r) {
            acc_word(a0, a1, v[r].x); acc_word(a2, a3, v[r].y);
            acc_word(a4, a5, v[r].z); acc_word(a6, a7, v[r].w);
        }
        // batch 2: 7 loads in flight (overlaps batch-1 accumulate retire)
        uint4 u[7];
#pragma unroll
        for (int r = 0; r < 7; ++r)
            u[r] = *reinterpret_cast<const uint4*>(
                pb + ((unsigned)ip[8 + r] * PROW + c_doff[8 + r]));
#pragma unroll
        for (int r = 0; r < 7; ++r) {
            acc_word(a0, a1, u[r].x); acc_word(a2, a3, u[r].y);
            acc_word(a4, a5, u[r].z); acc_word(a6, a7, u[r].w);
        }

        const int s = s_sp[m];
        int spn = (s <= 1) ? 1 : (s - 1);
        if (spn > 5) spn = 5;
        const __half2 sc2 = __float2half2_rn(c_scale[spn]);

        const uint4* spv = reinterpret_cast<const uint4*>(
            g_SPh + s * NH + chunk * 16);
        const uint4 sA = spv[0];
        const uint4 sB = spv[1];
        const __half2* sh  = reinterpret_cast<const __half2*>(&sA);
        const __half2* sh2 = reinterpret_cast<const __half2*>(&sB);

        __half2* dst = reinterpret_cast<__half2*>(&sval[m * 98 + chunk * 16]);
        dst[0] = __hfma2(a0, sc2, sh[0]);
        dst[1] = __hfma2(a1, sc2, sh[1]);
        dst[2] = __hfma2(a2, sc2, sh[2]);
        dst[3] = __hfma2(a3, sc2, sh[3]);
        dst[4] = __hfma2(a4, sc2, sh2[0]);
        dst[5] = __hfma2(a5, sc2, sh2[1]);
        dst[6] = __hfma2(a6, sc2, sh2[2]);
        dst[7] = __hfma2(a7, sc2, sh2[3]);
    }
    __syncthreads();

    // ---- write phase: warp w owns head pair hp = w + 8k, h = 2hp, 2hp+1 ----
#pragma unroll 1
    for (int k = 0; k < 6; ++k) {
        const int hp = warp + 8 * k;           // 0..47
        const int h0 = hp * 2;                 // even
        const float vw0 = s_virt[h0];
        const float vw1 = s_virt[h0 + 1];
        // h0 even -> h0&7 in {0,2,4,6}; h1 = h0+1 shares h>>3 -> ob1 = ob0+NSQ
        const size_t ob0 = ((((size_t)(h0 >> 3) * 16 + b) * 8) + (h0 & 7)) * NSQ
                           + (size_t)(n + 1) * NP1;
#pragma unroll
        for (int jj = 0; jj < 4; ++jj) {
            const int j = lane + 32 * jj;
            float lo, hi;
            if (j == 0) { lo = vw0; hi = vw1; }
            else {
                const __half2 hv = *reinterpret_cast<const __half2*>(
                    &sval[(j - 1) * 98 + h0]);
                lo = __low2float(hv); hi = __high2float(hv);
            }
            const float a2 = s_ab[j];
            out[ob0 + j]       = a2 + lo;
            out[ob0 + NSQ + j] = a2 + hi;
        }
        if (lane == 0) {
            const __half2 hv = *reinterpret_cast<const __half2*>(
                &sval[127 * 98 + h0]);
            out[ob0 + 128]       = s_ab[128] + __low2float(hv);
            out[ob0 + NSQ + 128] = s_ab[128] + __high2float(hv);
        }
    }
}

// ---------------------------------------------------------------------------
// Launch. Input order: attn_bias f32, spatial_pos i32, node_attr f32 (unused),
// edge_input i32, edge_enc_w f32, edge_dis_w f32, spatial_enc_w f32, virt_w
// f32. Output f32 [12,16,8,129,129].
// ---------------------------------------------------------------------------
extern "C" void kernel_launch(void* const* d_in, const int* in_sizes, int n_in,
                              void* d_out, int out_size) {
    const float* attn_bias     = (const float*)d_in[0];
    const int*   spatial_pos   = (const int*)  d_in[1];
    const int*   edge_input    = (const int*)  d_in[3];
    const float* edge_enc_w    = (const float*)d_in[4];
    const float* edge_dis_w    = (const float*)d_in[5];
    const float* spatial_enc_w = (const float*)d_in[6];
    const float* virt_w        = (const float*)d_in[7];
    float* out = (float*)d_out;

    prep_kernel<<<261, NH>>>(edge_enc_w, edge_dis_w, spatial_enc_w);
    main_kernel<<<dim3(129, 16), 256>>>(attn_bias, spatial_pos, edge_input,
                                        virt_w, out);
}

// round 7
// speedup vs baseline: 1.0745x; 1.0745x over previous
#include <cuda_runtime.h>
#include <cuda_bf16.h>
#include <cuda_fp16.h>
#include <cuda_fp8.h>
#include <cstdint>

// Problem constants
#define NH    96          // heads total
#define NEDGE 1537        // edge table rows (incl. padding row 0)
#define NDIST 5           // MULTI_HOP
#define NP1   129         // N+1
#define NSQ   (129*129)
#define PROW  128         // padded fp8 row stride (bytes)
#define DSTRIDE (NEDGE * PROW)   // bytes per distance table (fits int32)

#define P_SCALE 64.0f     // fp8 table pre-scale

// Projected edge table, fp8 e4m3, scaled by P_SCALE, row-padded to 128B.
__device__ __align__(128) unsigned char g_P8[(size_t)NDIST * DSTRIDE];
// Spatial bias table in fp16: 512*96 entries.
__device__ __align__(16) __half g_SPh[512 * NH];

// hop normalizer with the fp8 scale folded in: 1/(3*sp*P_SCALE)
__constant__ float c_scale[6] = {0.f,
    1.f/(3.f*P_SCALE), 1.f/(6.f*P_SCALE), 1.f/(9.f*P_SCALE),
    1.f/(12.f*P_SCALE), 1.f/(15.f*P_SCALE)};

// per-r table base offsets (d = r/3)
__constant__ unsigned c_doff[15] = {
    0, 0, 0,
    1u*DSTRIDE, 1u*DSTRIDE, 1u*DSTRIDE,
    2u*DSTRIDE, 2u*DSTRIDE, 2u*DSTRIDE,
    3u*DSTRIDE, 3u*DSTRIDE, 3u*DSTRIDE,
    4u*DSTRIDE, 4u*DSTRIDE, 4u*DSTRIDE};

// ---------------------------------------------------------------------------
// Kernel 1 (merged prep, R5 version): blocks 0..484 -> projected-table GEMM
// (16 edges per block); blocks 485..500 -> spatial f32->f16 convert.
// ---------------------------------------------------------------------------
__global__ void prep_kernel(const float* __restrict__ enc,
                            const float* __restrict__ dis,
                            const float* __restrict__ sp) {
    const int bx = blockIdx.x;
    const int h  = threadIdx.x;          // 0..95

    if (bx < 485) {
        __shared__ float s_enc[16 * 32];
        const int d  = bx / 97;
        const int e0 = (bx - d * 97) * 16;

        float w[32];
#pragma unroll
        for (int k = 0; k < 32; ++k)
            w[k] = dis[(d * 32 + k) * NH + h];

        for (int i = h; i < 16 * 32; i += 96) {
            const int e = e0 + (i >> 5);
            s_enc[i] = (e < NEDGE) ? enc[e * 32 + (i & 31)] : 0.f;
        }
        __syncthreads();

#pragma unroll 4
        for (int ei = 0; ei < 16; ++ei) {
            const int e = e0 + ei;
            if (e >= NEDGE) break;
            float acc = 0.f;
#pragma unroll
            for (int k = 0; k < 32; ++k)
                acc += s_enc[ei * 32 + k] * w[k];
            g_P8[(size_t)d * DSTRIDE + e * PROW + h] =
                __nv_cvt_float_to_fp8(acc * P_SCALE, __NV_SATFINITE, __NV_E4M3);
        }
    } else {
        const int t0 = ((bx - 485) * 96 + h) * 32;
#pragma unroll 8
        for (int k = 0; k < 32; ++k)
            g_SPh[t0 + k] = __float2half(sp[t0 + k]);
    }
}

// fp8x2 pair -> half2 accumulate (low / high 16 bits of a word)
__device__ __forceinline__ void acc_word(__half2& lo, __half2& hi, uint32_t w) {
    lo = __hadd2(lo, __half2(__nv_cvt_fp8x2_to_halfraw2(
             (__nv_fp8x2_storage_t)(unsigned short)w, __NV_E4M3)));
    hi = __hadd2(hi, __half2(__nv_cvt_fp8x2_to_halfraw2(
             (__nv_fp8x2_storage_t)(w >> 16), __NV_E4M3)));
}

// ---------------------------------------------------------------------------
// Kernel 2: main. grid (129, 16); n==128 is the virtual-token row.
// Gather: (m, 8-head chunk) flattened to 192 slots = 6 full-warp iterations;
//   each slot = 8 heads via LDG.64; the 15 row-gathers issue as two hoisted
//   batches (8 + 7 in flight). uint2 payload keeps live regs ~40 so six
//   256-thread CTAs fit per SM (occupancy-driven; L1 work unchanged).
// Write: warp w owns head-PAIR hp = w+8k, half2 smem reads, two contiguous
//   129-wide output rows per step.
// ---------------------------------------------------------------------------
__global__ __launch_bounds__(256, 6) void main_kernel(
    const float* __restrict__ attn_bias,
    const int*   __restrict__ spatial_pos,
    const int*   __restrict__ edge_input,
    const float* __restrict__ virt_w,
    float* __restrict__ out)
{
    const int n    = blockIdx.x;
    const int b    = blockIdx.y;
    const int tid  = threadIdx.x;

    if (n == 128) {
        for (int idx = tid; idx < NH * NP1; idx += 256) {
            const int h = idx / NP1;
            const int j = idx - h * NP1;
            const size_t o = ((((size_t)(h >> 3) * 16 + b) * 8) + (h & 7)) * NSQ + j;
            out[o] = 2.f * attn_bias[(size_t)b * NSQ + j] + virt_w[h];
        }
        return;
    }

    __shared__ __half sval[128 * 98];   // 196B row stride, conflict-free cols
    __shared__ int    s_idx[128 * 15];
    __shared__ int    s_sp[128];
    __shared__ float  s_ab[NP1];        // holds 2*attn_bias row
    __shared__ float  s_virt[NH];

    const int warp = tid >> 5;
    const int lane = tid & 31;
    const size_t bn = (size_t)(b * 128 + n) * 128;

    // stage indices: 1920 ints = 480 int4
    {
        const int4* gs = reinterpret_cast<const int4*>(edge_input + bn * 15);
        int4* ds = reinterpret_cast<int4*>(s_idx);
        ds[tid] = gs[tid];
        if (tid < 224) ds[256 + tid] = gs[256 + tid];
    }
    if (tid < 128) s_sp[tid] = spatial_pos[bn + tid];
    if (tid < NH)  s_virt[tid] = virt_w[tid];
    if (tid < NP1) s_ab[tid] = 2.f * attn_bias[(size_t)b * NSQ + (size_t)(n + 1) * NP1 + tid];
    __syncthreads();

    // ---- gather phase: 6 iterations x 32 lanes = 192 slots = 16 m x 12 chunks
    const __half2 hz = __float2half2_rn(0.f);
#pragma unroll
    for (int it = 0; it < 6; ++it) {
        const int slot  = it * 32 + lane;      // 0..191
        const int ml    = slot / 12;           // 0..15
        const int chunk = slot - ml * 12;      // 0..11 (8 bytes each)
        const int m     = warp * 16 + ml;
        const unsigned char* pb = g_P8 + chunk * 8;
        const int* ip = s_idx + m * 15;

        __half2 a0 = hz, a1 = hz, a2 = hz, a3 = hz;

        // batch 1: 8 LDG.64 in flight
        uint2 v[8];
#pragma unroll
        for (int r = 0; r < 8; ++r)
            v[r] = *reinterpret_cast<const uint2*>(
                pb + ((unsigned)ip[r] * PROW + c_doff[r]));
#pragma unroll
        for (int r = 0; r < 8; ++r) {
            acc_word(a0, a1, v[r].x); acc_word(a2, a3, v[r].y);
        }
        // batch 2: 7 LDG.64 in flight
        uint2 u[7];
#pragma unroll
        for (int r = 0; r < 7; ++r)
            u[r] = *reinterpret_cast<const uint2*>(
                pb + ((unsigned)ip[8 + r] * PROW + c_doff[8 + r]));
#pragma unroll
        for (int r = 0; r < 7; ++r) {
            acc_word(a0, a1, u[r].x); acc_word(a2, a3, u[r].y);
        }

        const int s = s_sp[m];
        int spn = (s <= 1) ? 1 : (s - 1);
        if (spn > 5) spn = 5;
        const __half2 sc2 = __float2half2_rn(c_scale[spn]);

        // spatial bias, 8 heads = 16B = 1x LDG.128 (16B aligned: 192s + 16c)
        const uint4 sA = *reinterpret_cast<const uint4*>(
            g_SPh + s * NH + chunk * 8);
        const __half2* sh = reinterpret_cast<const __half2*>(&sA);

        __half2* dst = reinterpret_cast<__half2*>(&sval[m * 98 + chunk * 8]);
        dst[0] = __hfma2(a0, sc2, sh[0]);
        dst[1] = __hfma2(a1, sc2, sh[1]);
        dst[2] = __hfma2(a2, sc2, sh[2]);
        dst[3] = __hfma2(a3, sc2, sh[3]);
    }
    __syncthreads();

    // ---- write phase: warp w owns head pair hp = w + 8k, h = 2hp, 2hp+1 ----
#pragma unroll 1
    for (int k = 0; k < 6; ++k) {
        const int hp = warp + 8 * k;           // 0..47
        const int h0 = hp * 2;                 // even
        const float vw0 = s_virt[h0];
        const float vw1 = s_virt[h0 + 1];
        const size_t ob0 = ((((size_t)(h0 >> 3) * 16 + b) * 8) + (h0 & 7)) * NSQ
                           + (size_t)(n + 1) * NP1;
#pragma unroll
        for (int jj = 0; jj < 4; ++jj) {
            const int j = lane + 32 * jj;
            float lo, hi;
            if (j == 0) { lo = vw0; hi = vw1; }
            else {
                const __half2 hv = *reinterpret_cast<const __half2*>(
                    &sval[(j - 1) * 98 + h0]);
                lo = __low2float(hv); hi = __high2float(hv);
            }
            const float a2 = s_ab[j];
            out[ob0 + j]       = a2 + lo;
            out[ob0 + NSQ + j] = a2 + hi;
        }
        if (lane == 0) {
            const __half2 hv = *reinterpret_cast<const __half2*>(
                &sval[127 * 98 + h0]);
            out[ob0 + 128]       = s_ab[128] + __low2float(hv);
            out[ob0 + NSQ + 128] = s_ab[128] + __high2float(hv);
        }
    }
}

// ---------------------------------------------------------------------------
// Launch. Input order: attn_bias f32, spatial_pos i32, node_attr f32 (unused),
// edge_input i32, edge_enc_w f32, edge_dis_w f32, spatial_enc_w f32, virt_w
// f32. Output f32 [12,16,8,129,129].
// ---------------------------------------------------------------------------
extern "C" void kernel_launch(void* const* d_in, const int* in_sizes, int n_in,
                              void* d_out, int out_size) {
    const float* attn_bias     = (const float*)d_in[0];
    const int*   spatial_pos   = (const int*)  d_in[1];
    const int*   edge_input    = (const int*)  d_in[3];
    const float* edge_enc_w    = (const float*)d_in[4];
    const float* edge_dis_w    = (const float*)d_in[5];
    const float* spatial_enc_w = (const float*)d_in[6];
    const float* virt_w        = (const float*)d_in[7];
    float* out = (float*)d_out;

    prep_kernel<<<501, NH>>>(edge_enc_w, edge_dis_w, spatial_enc_w);
    main_kernel<<<dim3(129, 16), 256>>>(attn_bias, spatial_pos, edge_input,
                                        virt_w, out);
}

// round 8
// speedup vs baseline: 1.1240x; 1.0461x over previous
#include <cuda_runtime.h>
#include <cuda_bf16.h>
#include <cuda_fp16.h>
#include <cuda_fp8.h>
#include <cstdint>

// Problem constants
#define NH    96          // heads total
#define NEDGE 1537        // edge table rows (incl. padding row 0)
#define NDIST 5           // MULTI_HOP
#define NP1   129         // N+1
#define NSQ   (129*129)
#define PROW  128         // padded fp8 row stride (bytes)
#define DSTRIDE (NEDGE * PROW)   // bytes per distance table (fits int32)

#define P_SCALE 64.0f     // fp8 table pre-scale

// Projected edge table, fp8 e4m3, scaled by P_SCALE, row-padded to 128B.
__device__ __align__(128) unsigned char g_P8[(size_t)NDIST * DSTRIDE];
// Spatial bias table in fp16: 512*96 entries.
__device__ __align__(16) __half g_SPh[512 * NH];

// hop normalizer with the fp8 scale folded in: 1/(3*sp*P_SCALE)
__constant__ float c_scale[6] = {0.f,
    1.f/(3.f*P_SCALE), 1.f/(6.f*P_SCALE), 1.f/(9.f*P_SCALE),
    1.f/(12.f*P_SCALE), 1.f/(15.f*P_SCALE)};

// per-r table base offsets (d = r/3), applied once at staging time
__constant__ unsigned c_doff[15] = {
    0, 0, 0,
    1u*DSTRIDE, 1u*DSTRIDE, 1u*DSTRIDE,
    2u*DSTRIDE, 2u*DSTRIDE, 2u*DSTRIDE,
    3u*DSTRIDE, 3u*DSTRIDE, 3u*DSTRIDE,
    4u*DSTRIDE, 4u*DSTRIDE, 4u*DSTRIDE};

// ---------------------------------------------------------------------------
// Kernel 1 (merged prep): blocks 0..484 -> projected-table GEMM (16 edges per
// block); blocks 485..500 -> spatial f32->f16 convert.
// ---------------------------------------------------------------------------
__global__ void prep_kernel(const float* __restrict__ enc,
                            const float* __restrict__ dis,
                            const float* __restrict__ sp) {
    const int bx = blockIdx.x;
    const int h  = threadIdx.x;          // 0..95

    if (bx < 485) {
        __shared__ float s_enc[16 * 32];
        const int d  = bx / 97;
        const int e0 = (bx - d * 97) * 16;

        float w[32];
#pragma unroll
        for (int k = 0; k < 32; ++k)
            w[k] = dis[(d * 32 + k) * NH + h];

        for (int i = h; i < 16 * 32; i += 96) {
            const int e = e0 + (i >> 5);
            s_enc[i] = (e < NEDGE) ? enc[e * 32 + (i & 31)] : 0.f;
        }
        __syncthreads();

#pragma unroll 4
        for (int ei = 0; ei < 16; ++ei) {
            const int e = e0 + ei;
            if (e >= NEDGE) break;
            float acc = 0.f;
#pragma unroll
            for (int k = 0; k < 32; ++k)
                acc += s_enc[ei * 32 + k] * w[k];
            g_P8[(size_t)d * DSTRIDE + e * PROW + h] =
                __nv_cvt_float_to_fp8(acc * P_SCALE, __NV_SATFINITE, __NV_E4M3);
        }
    } else {
        const int t0 = ((bx - 485) * 96 + h) * 32;
#pragma unroll 8
        for (int k = 0; k < 32; ++k)
            g_SPh[t0 + k] = __float2half(sp[t0 + k]);
    }
}

// fp8x2 pair -> half2 accumulate (low / high 16 bits of a word)
__device__ __forceinline__ void acc_word(__half2& lo, __half2& hi, uint32_t w) {
    lo = __hadd2(lo, __half2(__nv_cvt_fp8x2_to_halfraw2(
             (__nv_fp8x2_storage_t)(unsigned short)w, __NV_E4M3)));
    hi = __hadd2(hi, __half2(__nv_cvt_fp8x2_to_halfraw2(
             (__nv_fp8x2_storage_t)(w >> 16), __NV_E4M3)));
}

// pack raw edge index -> byte offset into g_P8 (row*128 + d-table base)
__device__ __forceinline__ int pack_off(int e, int p) {
    const int r = p % 15;
    return e * PROW + (int)c_doff[r];
}

// ---------------------------------------------------------------------------
// Kernel 2: main. grid (129, 16); n==128 is the virtual-token row.
// Gather: (m, 8-head chunk) flattened to 192 slots = 6 full-warp iterations;
//   all FIFTEEN row-gathers (LDG.64) issued back-to-back and in flight
//   (max per-warp MLP); addresses are pre-packed byte offsets computed once
//   during staging, so the hot loop is pure LDS+LDG+HADD2.
// Write: warp w owns head-PAIR hp = w+8k, half2 smem reads, two contiguous
//   129-wide output rows per step.
// ---------------------------------------------------------------------------
__global__ __launch_bounds__(256, 5) void main_kernel(
    const float* __restrict__ attn_bias,
    const int*   __restrict__ spatial_pos,
    const int*   __restrict__ edge_input,
    const float* __restrict__ virt_w,
    float* __restrict__ out)
{
    const int n    = blockIdx.x;
    const int b    = blockIdx.y;
    const int tid  = threadIdx.x;

    if (n == 128) {
        for (int idx = tid; idx < NH * NP1; idx += 256) {
            const int h = idx / NP1;
            const int j = idx - h * NP1;
            const size_t o = ((((size_t)(h >> 3) * 16 + b) * 8) + (h & 7)) * NSQ + j;
            out[o] = 2.f * attn_bias[(size_t)b * NSQ + j] + virt_w[h];
        }
        return;
    }

    __shared__ __half sval[128 * 98];   // 196B row stride, conflict-free cols
    __shared__ int    s_idx[128 * 15];  // PACKED byte offsets into g_P8
    __shared__ int    s_sp[128];
    __shared__ float  s_ab[NP1];        // holds 2*attn_bias row
    __shared__ float  s_virt[NH];

    const int warp = tid >> 5;
    const int lane = tid & 31;
    const size_t bn = (size_t)(b * 128 + n) * 128;

    // stage indices (1920 ints = 480 int4), packing row*128 + d*DSTRIDE
    {
        const int4* gs = reinterpret_cast<const int4*>(edge_input + bn * 15);
        int4* ds = reinterpret_cast<int4*>(s_idx);
        int4 q = gs[tid];
        int p = tid * 4;
        q.x = pack_off(q.x, p);
        q.y = pack_off(q.y, p + 1);
        q.z = pack_off(q.z, p + 2);
        q.w = pack_off(q.w, p + 3);
        ds[tid] = q;
        if (tid < 224) {
            int4 q2 = gs[256 + tid];
            p = (256 + tid) * 4;
            q2.x = pack_off(q2.x, p);
            q2.y = pack_off(q2.y, p + 1);
            q2.z = pack_off(q2.z, p + 2);
            q2.w = pack_off(q2.w, p + 3);
            ds[256 + tid] = q2;
        }
    }
    if (tid < 128) s_sp[tid] = spatial_pos[bn + tid];
    if (tid < NH)  s_virt[tid] = virt_w[tid];
    if (tid < NP1) s_ab[tid] = 2.f * attn_bias[(size_t)b * NSQ + (size_t)(n + 1) * NP1 + tid];
    __syncthreads();

    // ---- gather phase: 6 iterations x 32 lanes = 192 slots = 16 m x 12 chunks
    const __half2 hz = __float2half2_rn(0.f);
#pragma unroll
    for (int it = 0; it < 6; ++it) {
        const int slot  = it * 32 + lane;      // 0..191
        const int ml    = slot / 12;           // 0..15
        const int chunk = slot - ml * 12;      // 0..11 (8 bytes each)
        const int m     = warp * 16 + ml;
        const unsigned char* pb = g_P8 + chunk * 8;
        const int* ip = s_idx + m * 15;

        __half2 a0 = hz, a1 = hz, a2 = hz, a3 = hz;

        // all 15 LDG.64 in flight (max per-warp MLP)
        uint2 v[15];
#pragma unroll
        for (int r = 0; r < 15; ++r)
            v[r] = *reinterpret_cast<const uint2*>(pb + (unsigned)ip[r]);
#pragma unroll
        for (int r = 0; r < 15; ++r) {
            acc_word(a0, a1, v[r].x); acc_word(a2, a3, v[r].y);
        }

        const int s = s_sp[m];
        int spn = (s <= 1) ? 1 : (s - 1);
        if (spn > 5) spn = 5;
        const __half2 sc2 = __float2half2_rn(c_scale[spn]);

        // spatial bias, 8 heads = 16B = 1x LDG.128 (16B aligned)
        const uint4 sA = *reinterpret_cast<const uint4*>(
            g_SPh + s * NH + chunk * 8);
        const __half2* sh = reinterpret_cast<const __half2*>(&sA);

        __half2* dst = reinterpret_cast<__half2*>(&sval[m * 98 + chunk * 8]);
        dst[0] = __hfma2(a0, sc2, sh[0]);
        dst[1] = __hfma2(a1, sc2, sh[1]);
        dst[2] = __hfma2(a2, sc2, sh[2]);
        dst[3] = __hfma2(a3, sc2, sh[3]);
    }
    __syncthreads();

    // ---- write phase: warp w owns head pair hp = w + 8k, h = 2hp, 2hp+1 ----
#pragma unroll 1
    for (int k = 0; k < 6; ++k) {
        const int hp = warp + 8 * k;           // 0..47
        const int h0 = hp * 2;                 // even
        const float vw0 = s_virt[h0];
        const float vw1 = s_virt[h0 + 1];
        const size_t ob0 = ((((size_t)(h0 >> 3) * 16 + b) * 8) + (h0 & 7)) * NSQ
                           + (size_t)(n + 1) * NP1;
#pragma unroll
        for (int jj = 0; jj < 4; ++jj) {
            const int j = lane + 32 * jj;
            float lo, hi;
            if (j == 0) { lo = vw0; hi = vw1; }
            else {
                const __half2 hv = *reinterpret_cast<const __half2*>(
                    &sval[(j - 1) * 98 + h0]);
                lo = __low2float(hv); hi = __high2float(hv);
            }
            const float a2 = s_ab[j];
            out[ob0 + j]       = a2 + lo;
            out[ob0 + NSQ + j] = a2 + hi;
        }
        if (lane == 0) {
            const __half2 hv = *reinterpret_cast<const __half2*>(
                &sval[127 * 98 + h0]);
            out[ob0 + 128]       = s_ab[128] + __low2float(hv);
            out[ob0 + NSQ + 128] = s_ab[128] + __high2float(hv);
        }
    }
}

// ---------------------------------------------------------------------------
// Launch. Input order: attn_bias f32, spatial_pos i32, node_attr f32 (unused),
// edge_input i32, edge_enc_w f32, edge_dis_w f32, spatial_enc_w f32, virt_w
// f32. Output f32 [12,16,8,129,129].
// ---------------------------------------------------------------------------
extern "C" void kernel_launch(void* const* d_in, const int* in_sizes, int n_in,
                              void* d_out, int out_size) {
    const float* attn_bias     = (const float*)d_in[0];
    const int*   spatial_pos   = (const int*)  d_in[1];
    const int*   edge_input    = (const int*)  d_in[3];
    const float* edge_enc_w    = (const float*)d_in[4];
    const float* edge_dis_w    = (const float*)d_in[5];
    const float* spatial_enc_w = (const float*)d_in[6];
    const float* virt_w        = (const float*)d_in[7];
    float* out = (float*)d_out;

    prep_kernel<<<501, NH>>>(edge_enc_w, edge_dis_w, spatial_enc_w);
    main_kernel<<<dim3(129, 16), 256>>>(attn_bias, spatial_pos, edge_input,
                                        virt_w, out);
}